// round 3
// baseline (speedup 1.0000x reference)
#include <cuda_runtime.h>
#include <cstdint>

#define NN 50000
#define EE 800000

// ---------------- scratch (device globals; no allocation allowed) ----------------
__device__ float g_sq_a[NN * 2];
__device__ float g_sk_a[NN * 2];
__device__ float g_sq_b[NN * 2];
__device__ float g_sk_b[NN * 2];
__device__ float g_v1[NN * 64];     // v_a + rel1  (src values for relation 1)
__device__ float g_v2[NN * 64];     // v_b + rel2
__device__ float g_agg1[NN * 64];   // un-normalized Σ ex * v   (dst = b)
__device__ float g_agg2[NN * 64];   // dst = a
__device__ float g_t1[NN * 32];     // Σ ex * edge_attr  per (node, head)
__device__ float g_t2[NN * 32];
__device__ float g_den1[NN * 2];    // Σ ex
__device__ float g_den2[NN * 2];

// ---------------- helpers ----------------
__device__ __forceinline__ float tanh_fast(float x) {
    float y;
    asm("tanh.approx.f32 %0, %1;" : "=f"(y) : "f"(x));
    return y;
}
__device__ __forceinline__ void red4(float* p, float a, float b, float c, float d) {
    asm volatile("red.global.add.v4.f32 [%0], {%1,%2,%3,%4};"
                 :: "l"(p), "f"(a), "f"(b), "f"(c), "f"(d) : "memory");
}
__device__ __forceinline__ void red2(float* p, float a, float b) {
    asm volatile("red.global.add.v2.f32 [%0], {%1,%2};"
                 :: "l"(p), "f"(a), "f"(b) : "memory");
}

// ---------------- zero scratch ----------------
__global__ void zero_kernel() {
    int i = blockIdx.x * blockDim.x + threadIdx.x;
    int stride = gridDim.x * blockDim.x;
    for (int k = i; k < NN * 64; k += stride) { g_agg1[k] = 0.f; g_agg2[k] = 0.f; }
    for (int k = i; k < NN * 32; k += stride) { g_t1[k] = 0.f;  g_t2[k] = 0.f; }
    for (int k = i; k < NN * 2;  k += stride) { g_den1[k] = 0.f; g_den2[k] = 0.f; }
}

// ---------------- node precompute: sq, sk scalars + (v + rel) ----------------
// block = 256 threads, 64 nodes/block; thread = (node_local = tid/4, part p = tid%4, 16 cols each)
__global__ void __launch_bounds__(256) node_kernel(
    const float* __restrict__ x,  const float* __restrict__ Wq,
    const float* __restrict__ Wk, const float* __restrict__ Wv,
    const float* __restrict__ emb, const float* __restrict__ rel,
    const float* __restrict__ a_attn, int type)
{
    float* sq   = (type == 0) ? g_sq_a : g_sq_b;
    float* sk   = (type == 0) ? g_sk_a : g_sk_b;
    float* vout = (type == 0) ? g_v1   : g_v2;

    __shared__ float xs[64][65];
    __shared__ float Ws[64][64];
    __shared__ float embS[64], relS[64], aS[64];

    int tid = threadIdx.x;
    int nb  = blockIdx.x * 64;

    for (int i = tid; i < 4096; i += 256) {
        int rr = i >> 6, cc = i & 63;
        int n2 = nb + rr;
        xs[rr][cc] = (n2 < NN) ? x[n2 * 64 + cc] : 0.f;
        Ws[rr][cc] = Wq[i];
    }
    if (tid < 64) { embS[tid] = emb[tid]; relS[tid] = rel[tid]; aS[tid] = a_attn[tid]; }
    __syncthreads();

    int nl = tid >> 2, p = tid & 3, c0 = p * 16;
    int n = nb + nl;

    float xr[64];
#pragma unroll
    for (int j = 0; j < 64; j++) xr[j] = xs[nl][j];

    float acc[16];

    // ---- Q -> sq ----
#pragma unroll
    for (int i = 0; i < 16; i++) acc[i] = 0.f;
#pragma unroll 8
    for (int j = 0; j < 64; j++) {
        float xv = xr[j];
#pragma unroll
        for (int i = 0; i < 16; i++) acc[i] = fmaf(xv, Ws[j][c0 + i], acc[i]);
    }
    float pq = 0.f;
#pragma unroll
    for (int i = 0; i < 16; i++)
        pq += tanhf(acc[i] + embS[c0 + i]) * aS[(c0 + i) & 31];
    pq += __shfl_xor_sync(0xffffffffu, pq, 1);
    __syncthreads();

    // ---- K -> sk ----
    for (int i = tid; i < 4096; i += 256) Ws[i >> 6][i & 63] = Wk[i];
    __syncthreads();
#pragma unroll
    for (int i = 0; i < 16; i++) acc[i] = 0.f;
#pragma unroll 8
    for (int j = 0; j < 64; j++) {
        float xv = xr[j];
#pragma unroll
        for (int i = 0; i < 16; i++) acc[i] = fmaf(xv, Ws[j][c0 + i], acc[i]);
    }
    float pk = 0.f;
#pragma unroll
    for (int i = 0; i < 16; i++)
        pk += tanhf(acc[i] + embS[c0 + i]) * aS[32 + ((c0 + i) & 31)];
    pk += __shfl_xor_sync(0xffffffffu, pk, 1);

    if (n < NN) {
        if (p == 0)      { sq[n * 2]     = pq; sk[n * 2]     = pk; }
        else if (p == 2) { sq[n * 2 + 1] = pq; sk[n * 2 + 1] = pk; }
    }
    __syncthreads();

    // ---- V -> v + rel ----
    for (int i = tid; i < 4096; i += 256) Ws[i >> 6][i & 63] = Wv[i];
    __syncthreads();
#pragma unroll
    for (int i = 0; i < 16; i++) acc[i] = 0.f;
#pragma unroll 8
    for (int j = 0; j < 64; j++) {
        float xv = xr[j];
#pragma unroll
        for (int i = 0; i < 16; i++) acc[i] = fmaf(xv, Ws[j][c0 + i], acc[i]);
    }
    if (n < NN) {
        float4* vp = (float4*)(vout + (size_t)n * 64 + c0);
#pragma unroll
        for (int q4 = 0; q4 < 4; q4++)
            vp[q4] = make_float4(acc[q4 * 4 + 0] + relS[c0 + q4 * 4 + 0],
                                 acc[q4 * 4 + 1] + relS[c0 + q4 * 4 + 1],
                                 acc[q4 * 4 + 2] + relS[c0 + q4 * 4 + 2],
                                 acc[q4 * 4 + 3] + relS[c0 + q4 * 4 + 3]);
    }
}

// ---------------- single edge pass per relation ----------------
// thread per edge: eb = ea@We (1024 FMA), s_e = Σ tanh(eb)·a4, ex = exp(score),
// then vector reductions of ex, ex*ea, ex*v into dst-node accumulators.
__global__ void __launch_bounds__(256) edge_kernel(
    const float* __restrict__ ea, const int* __restrict__ row, const int* __restrict__ col,
    const float* __restrict__ We, const float* __restrict__ a_attn, int relid)
{
    const float* sq   = (relid == 0) ? g_sq_b : g_sq_a;   // destination-node q scalar
    const float* sk   = (relid == 0) ? g_sk_a : g_sk_b;   // source-node k scalar
    const float* vsrc = (relid == 0) ? g_v1   : g_v2;
    float* agg = (relid == 0) ? g_agg1 : g_agg2;
    float* tac = (relid == 0) ? g_t1   : g_t2;
    float* den = (relid == 0) ? g_den1 : g_den2;

    __shared__ float WeS[16][64];
    __shared__ float a4S[32];
    int tid = threadIdx.x;
    for (int i = tid; i < 1024; i += 256) WeS[i >> 6][i & 63] = We[i];
    if (tid < 32) a4S[tid] = a_attn[96 + tid];
    __syncthreads();

    int e = blockIdx.x * 256 + tid;
    if (e >= EE) return;
    int r = row[e], c = col[e];

    const float4* ea4 = (const float4*)ea + (size_t)e * 4;
    float4 A = ea4[0], B = ea4[1], C = ea4[2], D = ea4[3];
    float ear[16] = {A.x, A.y, A.z, A.w, B.x, B.y, B.z, B.w,
                     C.x, C.y, C.z, C.w, D.x, D.y, D.z, D.w};

    float se0 = 0.f, se1 = 0.f;
#pragma unroll 2
    for (int ch = 0; ch < 8; ch++) {
        float acc[8];
#pragma unroll
        for (int i = 0; i < 8; i++) acc[i] = 0.f;
#pragma unroll
        for (int j = 0; j < 16; j++) {
            float ev = ear[j];
#pragma unroll
            for (int i = 0; i < 8; i++)
                acc[i] = fmaf(ev, WeS[j][ch * 8 + i], acc[i]);
        }
        float s = 0.f;
#pragma unroll
        for (int i = 0; i < 8; i++)
            s += tanh_fast(acc[i]) * a4S[(ch * 8 + i) & 31];
        if (ch < 4) se0 += s; else se1 += s;
    }

    float2 sqv = __ldg((const float2*)sq + c);
    float2 skv = __ldg((const float2*)sk + r);
    float ex0 = __expf(sqv.x + skv.x + se0);
    float ex1 = __expf(sqv.y + skv.y + se1);

    red2(den + c * 2, ex0, ex1);

    float* tp = tac + (size_t)c * 32;
#pragma unroll
    for (int j4 = 0; j4 < 4; j4++)
        red4(tp + j4 * 4,
             ex0 * ear[j4 * 4], ex0 * ear[j4 * 4 + 1],
             ex0 * ear[j4 * 4 + 2], ex0 * ear[j4 * 4 + 3]);
#pragma unroll
    for (int j4 = 0; j4 < 4; j4++)
        red4(tp + 16 + j4 * 4,
             ex1 * ear[j4 * 4], ex1 * ear[j4 * 4 + 1],
             ex1 * ear[j4 * 4 + 2], ex1 * ear[j4 * 4 + 3]);

    const float4* v4 = (const float4*)vsrc + (size_t)r * 16;
    float* ap = agg + (size_t)c * 64;
#pragma unroll
    for (int k = 0; k < 16; k++) {
        float4 v = v4[k];
        float w = (k < 8) ? ex0 : ex1;
        red4(ap + k * 4, w * v.x, w * v.y, w * v.z, w * v.w);
    }
}

// ---------------- final: normalize + t@We + out = af@Wo + bo + x@Wr ----------------
// block = 256 threads, 32 nodes/block; part p = tid%8
__global__ void __launch_bounds__(256) final_kernel(
    const float* __restrict__ We, const float* __restrict__ Wo, const float* __restrict__ bo,
    const float* __restrict__ x,  const float* __restrict__ Wr,
    float* __restrict__ out, int type)
{
    const float* agg = (type == 0) ? g_agg2 : g_agg1;   // type 0 = a (relation 2 output)
    const float* tac = (type == 0) ? g_t2   : g_t1;
    const float* den = (type == 0) ? g_den2 : g_den1;

    __shared__ float afs[32][65];
    __shared__ float xs[32][65];
    __shared__ float WoS[64][32];
    __shared__ float WrS[64][32];
    __shared__ float WeS[16][64];
    __shared__ float tS[32][33];
    __shared__ float denS[32][2];
    __shared__ float boS[32];

    int tid = threadIdx.x;
    int nb  = blockIdx.x * 32;

    for (int i = tid; i < 2048; i += 256) {
        WoS[i >> 5][i & 31] = Wo[i];
        WrS[i >> 5][i & 31] = Wr[i];
        int n2 = nb + (i >> 6), c2 = i & 63;
        afs[i >> 6][c2] = (n2 < NN) ? agg[(size_t)n2 * 64 + c2] : 0.f;
        xs[i >> 6][c2]  = (n2 < NN) ? x[(size_t)n2 * 64 + c2]   : 0.f;
    }
    for (int i = tid; i < 1024; i += 256) {
        WeS[i >> 6][i & 63] = We[i];
        int n2 = nb + (i >> 5);
        tS[i >> 5][i & 31] = (n2 < NN) ? tac[(size_t)n2 * 32 + (i & 31)] : 0.f;
    }
    if (tid < 64) {
        int n2 = nb + (tid >> 1);
        denS[tid >> 1][tid & 1] = (n2 < NN) ? den[n2 * 2 + (tid & 1)] : 0.f;
    }
    if (tid < 32) boS[tid] = bo[tid];
    __syncthreads();

    int nl = tid >> 3, p = tid & 7;
    int n = nb + nl;

    // phase 1: af[c] = (agg_raw + t@We) / den  (0 if no incoming edges; rel already in v)
    float af[8];
#pragma unroll
    for (int i = 0; i < 8; i++) {
        int cc = p * 8 + i;
        int h = cc >> 5;
        float d = denS[nl][h];
        float tw = afs[nl][cc];
#pragma unroll
        for (int j = 0; j < 16; j++)
            tw = fmaf(tS[nl][h * 16 + j], WeS[j][cc], tw);
        af[i] = (d > 0.f) ? tw / d : 0.f;
    }
    __syncthreads();
#pragma unroll
    for (int i = 0; i < 8; i++) afs[nl][p * 8 + i] = af[i];
    __syncthreads();

    // phase 2: out = af @ Wo + bo + x @ Wr
    float o[4];
#pragma unroll
    for (int i = 0; i < 4; i++) o[i] = boS[p * 4 + i];
#pragma unroll 8
    for (int k = 0; k < 64; k++) {
        float a  = afs[nl][k];
        float xv = xs[nl][k];
#pragma unroll
        for (int i = 0; i < 4; i++) {
            o[i] = fmaf(a,  WoS[k][p * 4 + i], o[i]);
            o[i] = fmaf(xv, WrS[k][p * 4 + i], o[i]);
        }
    }
    if (n < NN) {
        float4* op = (float4*)(out + (size_t)n * 32 + p * 4);
        op[0] = make_float4(o[0], o[1], o[2], o[3]);
    }
}

// ---------------- launch ----------------
extern "C" void kernel_launch(void* const* d_in, const int* in_sizes, int n_in,
                              void* d_out, int out_size)
{
    const float* x_a    = (const float*)d_in[0];
    const float* x_b    = (const float*)d_in[1];
    const float* ea1    = (const float*)d_in[2];
    const float* ea2    = (const float*)d_in[3];
    const float* Wq_a   = (const float*)d_in[4];
    const float* Wk_a   = (const float*)d_in[5];
    const float* Wv_a   = (const float*)d_in[6];
    const float* Wq_b   = (const float*)d_in[7];
    const float* Wk_b   = (const float*)d_in[8];
    const float* Wv_b   = (const float*)d_in[9];
    const float* emb_a  = (const float*)d_in[10];
    const float* emb_b  = (const float*)d_in[11];
    const float* rel1   = (const float*)d_in[12];
    const float* rel2   = (const float*)d_in[13];
    const float* We     = (const float*)d_in[14];
    const float* a_attn = (const float*)d_in[15];
    const float* Wo_a   = (const float*)d_in[16];
    const float* bo_a   = (const float*)d_in[17];
    const float* Wo_b   = (const float*)d_in[18];
    const float* bo_b   = (const float*)d_in[19];
    const float* Wr_a   = (const float*)d_in[20];
    const float* Wr_b   = (const float*)d_in[21];
    const int*   row1   = (const int*)d_in[22];
    const int*   col1   = (const int*)d_in[23];
    const int*   row2   = (const int*)d_in[24];
    const int*   col2   = (const int*)d_in[25];
    float* out = (float*)d_out;

    zero_kernel<<<2048, 256>>>();

    node_kernel<<<(NN + 63) / 64, 256>>>(x_a, Wq_a, Wk_a, Wv_a, emb_a, rel1, a_attn, 0);
    node_kernel<<<(NN + 63) / 64, 256>>>(x_b, Wq_b, Wk_b, Wv_b, emb_b, rel2, a_attn, 1);

    edge_kernel<<<(EE + 255) / 256, 256>>>(ea1, row1, col1, We, a_attn, 0);
    edge_kernel<<<(EE + 255) / 256, 256>>>(ea2, row2, col2, We, a_attn, 1);

    final_kernel<<<(NN + 31) / 32, 256>>>(We, Wo_a, bo_a, x_a, Wr_a, out, 0);
    final_kernel<<<(NN + 31) / 32, 256>>>(We, Wo_b, bo_b, x_b, Wr_b, out + (size_t)NN * 32, 1);
}

// round 4
// speedup vs baseline: 1.2040x; 1.2040x over previous
#include <cuda_runtime.h>
#include <cstdint>

#define NN 50000
#define EE 800000
#define ZB 256          // zeroing blocks in prep kernel
#define NB 782          // node blocks per type: ceil(50000/64)
#define EB 25000        // edge blocks per relation: 800000/32

// ---------------- scratch (device globals; no allocation allowed) ----------------
__device__ __align__(16) float g_sq_a[NN * 2];
__device__ __align__(16) float g_sk_a[NN * 2];
__device__ __align__(16) float g_sq_b[NN * 2];
__device__ __align__(16) float g_sk_b[NN * 2];
__device__ __align__(16) float g_v1[NN * 64];     // v_a + rel1  (src values, relation 1)
__device__ __align__(16) float g_v2[NN * 64];     // v_b + rel2
__device__ __align__(16) float g_agg1[NN * 64];   // Σ ex * v   (dst = b)
__device__ __align__(16) float g_agg2[NN * 64];   // dst = a
__device__ __align__(16) float g_t1[NN * 32];     // Σ ex * edge_attr per (node, head)
__device__ __align__(16) float g_t2[NN * 32];
__device__ __align__(16) float g_den1[NN * 2];    // Σ ex
__device__ __align__(16) float g_den2[NN * 2];

// ---------------- helpers ----------------
__device__ __forceinline__ float tanh_fast(float x) {
    float y;
    asm("tanh.approx.f32 %0, %1;" : "=f"(y) : "f"(x));
    return y;
}
__device__ __forceinline__ void red4(float* p, float a, float b, float c, float d) {
    asm volatile("red.global.add.v4.f32 [%0], {%1,%2,%3,%4};"
                 :: "l"(p), "f"(a), "f"(b), "f"(c), "f"(d) : "memory");
}
__device__ __forceinline__ void red2(float* p, float a, float b) {
    asm volatile("red.global.add.v2.f32 [%0], {%1,%2};"
                 :: "l"(p), "f"(a), "f"(b) : "memory");
}

// ---------------- prep: zero scratch + node precompute (sq, sk, v+rel) ----------------
// blocks [0,ZB): zeroing.  blocks [ZB, ZB+NB): type a.  [ZB+NB, ZB+2NB): type b.
__global__ void __launch_bounds__(256) prep_kernel(
    const float* __restrict__ x_a, const float* __restrict__ Wq_a,
    const float* __restrict__ Wk_a, const float* __restrict__ Wv_a,
    const float* __restrict__ x_b, const float* __restrict__ Wq_b,
    const float* __restrict__ Wk_b, const float* __restrict__ Wv_b,
    const float* __restrict__ emb_a, const float* __restrict__ emb_b,
    const float* __restrict__ rel1, const float* __restrict__ rel2,
    const float* __restrict__ a_attn)
{
    int b = blockIdx.x;
    int tid = threadIdx.x;

    if (b < ZB) {
        const float4 z = make_float4(0.f, 0.f, 0.f, 0.f);
        int i = b * 256 + tid;
        const int S = ZB * 256;
        for (int k = i; k < NN * 16; k += S) { ((float4*)g_agg1)[k] = z; ((float4*)g_agg2)[k] = z; }
        for (int k = i; k < NN * 8;  k += S) { ((float4*)g_t1)[k]   = z; ((float4*)g_t2)[k]   = z; }
        for (int k = i; k < NN / 2;  k += S) { ((float4*)g_den1)[k] = z; ((float4*)g_den2)[k] = z; }
        return;
    }
    b -= ZB;
    int type = (b >= NB) ? 1 : 0;
    if (type) b -= NB;

    const float* x   = type ? x_b  : x_a;
    const float* Wq  = type ? Wq_b : Wq_a;
    const float* Wk  = type ? Wk_b : Wk_a;
    const float* Wv  = type ? Wv_b : Wv_a;
    const float* emb = type ? emb_b : emb_a;
    const float* rel = type ? rel2 : rel1;
    float* sq   = type ? g_sq_b : g_sq_a;
    float* sk   = type ? g_sk_b : g_sk_a;
    float* vout = type ? g_v2   : g_v1;

    __shared__ float xs[64][65];
    __shared__ float Ws[64][64];
    __shared__ float embS[64], relS[64], aS[64];

    int nb = b * 64;

    for (int i = tid; i < 4096; i += 256) {
        int rr = i >> 6, cc = i & 63;
        int n2 = nb + rr;
        xs[rr][cc] = (n2 < NN) ? x[n2 * 64 + cc] : 0.f;
        Ws[rr][cc] = Wq[i];
    }
    if (tid < 64) { embS[tid] = emb[tid]; relS[tid] = rel[tid]; aS[tid] = a_attn[tid]; }
    __syncthreads();

    int nl = tid >> 2, p = tid & 3, c0 = p * 16;
    int n = nb + nl;

    float acc[16];

    // ---- Q -> sq ----
#pragma unroll
    for (int i = 0; i < 16; i++) acc[i] = 0.f;
#pragma unroll 16
    for (int j = 0; j < 64; j++) {
        float xv = xs[nl][j];
#pragma unroll
        for (int i = 0; i < 16; i++) acc[i] = fmaf(xv, Ws[j][c0 + i], acc[i]);
    }
    float pq = 0.f;
#pragma unroll
    for (int i = 0; i < 16; i++)
        pq += tanh_fast(acc[i] + embS[c0 + i]) * aS[(c0 + i) & 31];
    pq += __shfl_xor_sync(0xffffffffu, pq, 1);
    __syncthreads();

    // ---- K -> sk ----
    for (int i = tid; i < 4096; i += 256) Ws[i >> 6][i & 63] = Wk[i];
    __syncthreads();
#pragma unroll
    for (int i = 0; i < 16; i++) acc[i] = 0.f;
#pragma unroll 16
    for (int j = 0; j < 64; j++) {
        float xv = xs[nl][j];
#pragma unroll
        for (int i = 0; i < 16; i++) acc[i] = fmaf(xv, Ws[j][c0 + i], acc[i]);
    }
    float pk = 0.f;
#pragma unroll
    for (int i = 0; i < 16; i++)
        pk += tanh_fast(acc[i] + embS[c0 + i]) * aS[32 + ((c0 + i) & 31)];
    pk += __shfl_xor_sync(0xffffffffu, pk, 1);

    if (n < NN) {
        if (p == 0)      { sq[n * 2]     = pq; sk[n * 2]     = pk; }
        else if (p == 2) { sq[n * 2 + 1] = pq; sk[n * 2 + 1] = pk; }
    }
    __syncthreads();

    // ---- V -> v + rel ----
    for (int i = tid; i < 4096; i += 256) Ws[i >> 6][i & 63] = Wv[i];
    __syncthreads();
#pragma unroll
    for (int i = 0; i < 16; i++) acc[i] = 0.f;
#pragma unroll 16
    for (int j = 0; j < 64; j++) {
        float xv = xs[nl][j];
#pragma unroll
        for (int i = 0; i < 16; i++) acc[i] = fmaf(xv, Ws[j][c0 + i], acc[i]);
    }
    if (n < NN) {
        float4* vp = (float4*)(vout + (size_t)n * 64 + c0);
#pragma unroll
        for (int q4 = 0; q4 < 4; q4++)
            vp[q4] = make_float4(acc[q4 * 4 + 0] + relS[c0 + q4 * 4 + 0],
                                 acc[q4 * 4 + 1] + relS[c0 + q4 * 4 + 1],
                                 acc[q4 * 4 + 2] + relS[c0 + q4 * 4 + 2],
                                 acc[q4 * 4 + 3] + relS[c0 + q4 * 4 + 3]);
    }
}

// ---------------- merged edge pass: 8 threads per edge, both relations ----------------
__global__ void __launch_bounds__(256) edge_kernel(
    const float* __restrict__ ea1, const int* __restrict__ row1, const int* __restrict__ col1,
    const float* __restrict__ ea2, const int* __restrict__ row2, const int* __restrict__ col2,
    const float* __restrict__ We, const float* __restrict__ a_attn)
{
    int bb = blockIdx.x;
    int relid = (bb >= EB) ? 1 : 0;
    if (relid) bb -= EB;

    const float* ea  = relid ? ea2  : ea1;
    const int*   row = relid ? row2 : row1;
    const int*   col = relid ? col2 : col1;
    const float* sq  = relid ? g_sq_a : g_sq_b;   // destination-node q scalar
    const float* sk  = relid ? g_sk_b : g_sk_a;   // source-node k scalar
    const float* vsrc = relid ? g_v2 : g_v1;
    float* agg = relid ? g_agg2 : g_agg1;
    float* tac = relid ? g_t2   : g_t1;
    float* den = relid ? g_den2 : g_den1;

    __shared__ float WeS[16][64];
    __shared__ float a4S[32];
    int tid = threadIdx.x;
    for (int i = tid; i < 1024; i += 256) WeS[i >> 6][i & 63] = We[i];
    if (tid < 32) a4S[tid] = a_attn[96 + tid];
    __syncthreads();

    int lane = tid & 7;
    int e = bb * 32 + (tid >> 3);
    int r = __ldg(row + e), c = __ldg(col + e);

    // full ea row (broadcast within 8-lane group; cheap sector count per warp)
    const float4* ea4p = (const float4*)ea + (size_t)e * 4;
    float4 A = __ldg(ea4p), B = __ldg(ea4p + 1), C = __ldg(ea4p + 2), D = __ldg(ea4p + 3);
    float ear[16] = {A.x, A.y, A.z, A.w, B.x, B.y, B.z, B.w,
                     C.x, C.y, C.z, C.w, D.x, D.y, D.z, D.w};

    // eb GEMV: this thread computes cols {lane + 8i}, i = 0..7  (conflict-free smem)
    float acc[8];
#pragma unroll
    for (int i = 0; i < 8; i++) acc[i] = 0.f;
#pragma unroll
    for (int j = 0; j < 16; j++) {
        float ev = ear[j];
#pragma unroll
        for (int i = 0; i < 8; i++)
            acc[i] = fmaf(ev, WeS[j][lane + 8 * i], acc[i]);
    }
    float se0 = 0.f, se1 = 0.f;
#pragma unroll
    for (int i = 0; i < 4; i++)
        se0 += tanh_fast(acc[i]) * a4S[lane + 8 * i];                 // cols < 32 (head 0)
#pragma unroll
    for (int i = 4; i < 8; i++)
        se1 += tanh_fast(acc[i]) * a4S[(lane + 8 * i) & 31];          // cols 32..63 (head 1)
#pragma unroll
    for (int m = 1; m < 8; m <<= 1) {
        se0 += __shfl_xor_sync(0xffffffffu, se0, m);
        se1 += __shfl_xor_sync(0xffffffffu, se1, m);
    }

    float2 sqv = __ldg((const float2*)sq + c);
    float2 skv = __ldg((const float2*)sk + r);
    float ex0 = __expf(sqv.x + skv.x + se0);
    float ex1 = __expf(sqv.y + skv.y + se1);

    if (lane == 0) red2(den + c * 2, ex0, ex1);

    // t scatter: 32 floats per edge, 4 per lane, contiguous across the 8-lane group
    {
        int q = lane & 3;
        float4 eaq = (q == 0) ? A : (q == 1) ? B : (q == 2) ? C : D;
        float exh = (lane < 4) ? ex0 : ex1;
        red4(tac + (size_t)c * 32 + (lane >> 2) * 16 + q * 4,
             exh * eaq.x, exh * eaq.y, exh * eaq.z, exh * eaq.w);
    }

    // coalesced v gather (contiguous 128B per 8-lane group) + contiguous agg scatter
    const float4* vp = (const float4*)vsrc + (size_t)r * 16 + lane * 2;
    float4 v0 = __ldg(vp), v1 = __ldg(vp + 1);
    float w = (lane < 4) ? ex0 : ex1;
    float* ap = agg + (size_t)c * 64 + lane * 8;
    red4(ap,     w * v0.x, w * v0.y, w * v0.z, w * v0.w);
    red4(ap + 4, w * v1.x, w * v1.y, w * v1.z, w * v1.w);
}

// ---------------- final: normalize + t@We + out = af@Wo + bo + x@Wr (both types) ----------------
__global__ void __launch_bounds__(256) final_kernel(
    const float* __restrict__ We,
    const float* __restrict__ Wo_a, const float* __restrict__ bo_a,
    const float* __restrict__ x_a,  const float* __restrict__ Wr_a,
    const float* __restrict__ Wo_b, const float* __restrict__ bo_b,
    const float* __restrict__ x_b,  const float* __restrict__ Wr_b,
    float* __restrict__ out)
{
    int type = blockIdx.y;   // 0 = a, 1 = b
    const float* Wo = type ? Wo_b : Wo_a;
    const float* bo = type ? bo_b : bo_a;
    const float* x  = type ? x_b  : x_a;
    const float* Wr = type ? Wr_b : Wr_a;
    const float* agg = type ? g_agg1 : g_agg2;   // a's messages come from relation 2
    const float* tac = type ? g_t1   : g_t2;
    const float* den = type ? g_den1 : g_den2;
    float* outp = out + (size_t)type * NN * 32;

    __shared__ float afs[32][65];
    __shared__ float xs[32][65];
    __shared__ float WoS[64][32];
    __shared__ float WrS[64][32];
    __shared__ float WeS[16][64];
    __shared__ float tS[32][33];
    __shared__ float denS[32][2];
    __shared__ float boS[32];

    int tid = threadIdx.x;
    int nb  = blockIdx.x * 32;

    for (int i = tid; i < 2048; i += 256) {
        WoS[i >> 5][i & 31] = Wo[i];
        WrS[i >> 5][i & 31] = Wr[i];
        int n2 = nb + (i >> 6), c2 = i & 63;
        afs[i >> 6][c2] = (n2 < NN) ? agg[(size_t)n2 * 64 + c2] : 0.f;
        xs[i >> 6][c2]  = (n2 < NN) ? x[(size_t)n2 * 64 + c2]   : 0.f;
    }
    for (int i = tid; i < 1024; i += 256) {
        WeS[i >> 6][i & 63] = We[i];
        int n2 = nb + (i >> 5);
        tS[i >> 5][i & 31] = (n2 < NN) ? tac[(size_t)n2 * 32 + (i & 31)] : 0.f;
    }
    if (tid < 64) {
        int n2 = nb + (tid >> 1);
        denS[tid >> 1][tid & 1] = (n2 < NN) ? den[n2 * 2 + (tid & 1)] : 0.f;
    }
    if (tid < 32) boS[tid] = bo[tid];
    __syncthreads();

    int nl = tid >> 3, p = tid & 7;
    int n = nb + nl;

    // phase 1: af[c] = (agg_raw + t@We) / den  (0 if no incoming edges)
    float af[8];
#pragma unroll
    for (int i = 0; i < 8; i++) {
        int cc = p * 8 + i;
        int h = cc >> 5;
        float d = denS[nl][h];
        float tw = afs[nl][cc];
#pragma unroll
        for (int j = 0; j < 16; j++)
            tw = fmaf(tS[nl][h * 16 + j], WeS[j][cc], tw);
        af[i] = (d > 0.f) ? tw / d : 0.f;
    }
    __syncthreads();
#pragma unroll
    for (int i = 0; i < 8; i++) afs[nl][p * 8 + i] = af[i];
    __syncthreads();

    // phase 2: out = af @ Wo + bo + x @ Wr
    float o[4];
#pragma unroll
    for (int i = 0; i < 4; i++) o[i] = boS[p * 4 + i];
#pragma unroll 8
    for (int k = 0; k < 64; k++) {
        float a  = afs[nl][k];
        float xv = xs[nl][k];
#pragma unroll
        for (int i = 0; i < 4; i++) {
            o[i] = fmaf(a,  WoS[k][p * 4 + i], o[i]);
            o[i] = fmaf(xv, WrS[k][p * 4 + i], o[i]);
        }
    }
    if (n < NN) {
        float4* op = (float4*)(outp + (size_t)n * 32 + p * 4);
        op[0] = make_float4(o[0], o[1], o[2], o[3]);
    }
}

// ---------------- launch ----------------
extern "C" void kernel_launch(void* const* d_in, const int* in_sizes, int n_in,
                              void* d_out, int out_size)
{
    const float* x_a    = (const float*)d_in[0];
    const float* x_b    = (const float*)d_in[1];
    const float* ea1    = (const float*)d_in[2];
    const float* ea2    = (const float*)d_in[3];
    const float* Wq_a   = (const float*)d_in[4];
    const float* Wk_a   = (const float*)d_in[5];
    const float* Wv_a   = (const float*)d_in[6];
    const float* Wq_b   = (const float*)d_in[7];
    const float* Wk_b   = (const float*)d_in[8];
    const float* Wv_b   = (const float*)d_in[9];
    const float* emb_a  = (const float*)d_in[10];
    const float* emb_b  = (const float*)d_in[11];
    const float* rel1   = (const float*)d_in[12];
    const float* rel2   = (const float*)d_in[13];
    const float* We     = (const float*)d_in[14];
    const float* a_attn = (const float*)d_in[15];
    const float* Wo_a   = (const float*)d_in[16];
    const float* bo_a   = (const float*)d_in[17];
    const float* Wo_b   = (const float*)d_in[18];
    const float* bo_b   = (const float*)d_in[19];
    const float* Wr_a   = (const float*)d_in[20];
    const float* Wr_b   = (const float*)d_in[21];
    const int*   row1   = (const int*)d_in[22];
    const int*   col1   = (const int*)d_in[23];
    const int*   row2   = (const int*)d_in[24];
    const int*   col2   = (const int*)d_in[25];
    float* out = (float*)d_out;

    prep_kernel<<<ZB + 2 * NB, 256>>>(x_a, Wq_a, Wk_a, Wv_a,
                                      x_b, Wq_b, Wk_b, Wv_b,
                                      emb_a, emb_b, rel1, rel2, a_attn);

    edge_kernel<<<2 * EB, 256>>>(ea1, row1, col1, ea2, row2, col2, We, a_attn);

    dim3 fg((NN + 31) / 32, 2);
    final_kernel<<<fg, 256>>>(We, Wo_a, bo_a, x_a, Wr_a,
                              Wo_b, bo_b, x_b, Wr_b, out);
}

// round 5
// speedup vs baseline: 1.9234x; 1.5975x over previous
#include <cuda_runtime.h>
#include <cstdint>

#define NN 50000
#define EE 800000
#define ZB 256          // zeroing blocks in prep kernel
#define NB 782          // node blocks per type: ceil(50000/64)
#define EGB 6250        // edge blocks per relation (128 edges/block)

// ---------------- scratch (device globals; no allocation allowed) ----------------
__device__ __align__(16) float g_sq_a[NN * 2];
__device__ __align__(16) float g_sk_a[NN * 2];
__device__ __align__(16) float g_sq_b[NN * 2];
__device__ __align__(16) float g_sk_b[NN * 2];
__device__ __align__(16) float g_v1[NN * 64];     // permuted (v_a + rel1)
__device__ __align__(16) float g_v2[NN * 64];     // permuted (v_b + rel2)
__device__ __align__(16) float g_agg1[NN * 64];   // permuted Σ ex*(v+rel+eb), dst = b
__device__ __align__(16) float g_agg2[NN * 64];   // dst = a
__device__ __align__(16) float g_den1[NN * 2];    // Σ ex
__device__ __align__(16) float g_den2[NN * 2];

// permutation: storage index s holds column pi(s) = (s%8)*8 + s/8  (involution)

// ---------------- helpers ----------------
__device__ __forceinline__ float tanh_fast(float x) {
    float y;
    asm("tanh.approx.f32 %0, %1;" : "=f"(y) : "f"(x));
    return y;
}
__device__ __forceinline__ void red4(float* p, float a, float b, float c, float d) {
    asm volatile("red.global.add.v4.f32 [%0], {%1,%2,%3,%4};"
                 :: "l"(p), "f"(a), "f"(b), "f"(c), "f"(d) : "memory");
}
__device__ __forceinline__ void red2(float* p, float a, float b) {
    asm volatile("red.global.add.v2.f32 [%0], {%1,%2};"
                 :: "l"(p), "f"(a), "f"(b) : "memory");
}

// ---------------- prep: zero scratch + fused-QKV node precompute ----------------
// dynamic smem: xs[64*65] | Wq[4096] | Wk[4096] | Wv[4096] | emb[64] | rel[64] | a[64]
#define PREP_SMEM ((4160 + 3 * 4096 + 192) * 4)

__global__ void __launch_bounds__(256) prep_kernel(
    const float* __restrict__ x_a, const float* __restrict__ Wq_a,
    const float* __restrict__ Wk_a, const float* __restrict__ Wv_a,
    const float* __restrict__ x_b, const float* __restrict__ Wq_b,
    const float* __restrict__ Wk_b, const float* __restrict__ Wv_b,
    const float* __restrict__ emb_a, const float* __restrict__ emb_b,
    const float* __restrict__ rel1, const float* __restrict__ rel2,
    const float* __restrict__ a_attn)
{
    int b = blockIdx.x;
    int tid = threadIdx.x;

    if (b < ZB) {
        const float4 z = make_float4(0.f, 0.f, 0.f, 0.f);
        int i = b * 256 + tid;
        const int S = ZB * 256;
        for (int k = i; k < NN * 16; k += S) { ((float4*)g_agg1)[k] = z; ((float4*)g_agg2)[k] = z; }
        for (int k = i; k < NN / 2;  k += S) { ((float4*)g_den1)[k] = z; ((float4*)g_den2)[k] = z; }
        return;
    }
    b -= ZB;
    int type = (b >= NB) ? 1 : 0;
    if (type) b -= NB;

    const float* x   = type ? x_b  : x_a;
    const float* Wqg = type ? Wq_b : Wq_a;
    const float* Wkg = type ? Wk_b : Wk_a;
    const float* Wvg = type ? Wv_b : Wv_a;
    const float* emb = type ? emb_b : emb_a;
    const float* rel = type ? rel2 : rel1;
    float* sq   = type ? g_sq_b : g_sq_a;
    float* sk   = type ? g_sk_b : g_sk_a;
    float* vout = type ? g_v2   : g_v1;

    extern __shared__ float sm[];
    float* xs   = sm;              // 64 x 65
    float* Wq   = sm + 4160;
    float* Wk   = Wq + 4096;
    float* Wv   = Wk + 4096;
    float* embS = Wv + 4096;
    float* relS = embS + 64;
    float* aS   = relS + 64;

    int nb = b * 64;

    for (int i = tid; i < 4096; i += 256) {
        int rr = i >> 6, cc = i & 63;
        int n2 = nb + rr;
        xs[rr * 65 + cc] = (n2 < NN) ? __ldg(x + n2 * 64 + cc) : 0.f;
        Wq[i] = __ldg(Wqg + i);
        Wk[i] = __ldg(Wkg + i);
        Wv[i] = __ldg(Wvg + i);
    }
    if (tid < 64) { embS[tid] = emb[tid]; relS[tid] = rel[tid]; aS[tid] = a_attn[tid]; }
    __syncthreads();

    int g = tid >> 4, cg = tid & 15, c0 = cg * 4;

    float aq[16], ak[16], av[16];
#pragma unroll
    for (int i = 0; i < 16; i++) { aq[i] = 0.f; ak[i] = 0.f; av[i] = 0.f; }

#pragma unroll 8
    for (int j = 0; j < 64; j++) {
        float4 wq = *(const float4*)&Wq[j * 64 + c0];
        float4 wk = *(const float4*)&Wk[j * 64 + c0];
        float4 wv = *(const float4*)&Wv[j * 64 + c0];
#pragma unroll
        for (int r = 0; r < 4; r++) {
            float xv = xs[(g * 4 + r) * 65 + j];
            aq[r*4+0] = fmaf(xv, wq.x, aq[r*4+0]);
            aq[r*4+1] = fmaf(xv, wq.y, aq[r*4+1]);
            aq[r*4+2] = fmaf(xv, wq.z, aq[r*4+2]);
            aq[r*4+3] = fmaf(xv, wq.w, aq[r*4+3]);
            ak[r*4+0] = fmaf(xv, wk.x, ak[r*4+0]);
            ak[r*4+1] = fmaf(xv, wk.y, ak[r*4+1]);
            ak[r*4+2] = fmaf(xv, wk.z, ak[r*4+2]);
            ak[r*4+3] = fmaf(xv, wk.w, ak[r*4+3]);
            av[r*4+0] = fmaf(xv, wv.x, av[r*4+0]);
            av[r*4+1] = fmaf(xv, wv.y, av[r*4+1]);
            av[r*4+2] = fmaf(xv, wv.z, av[r*4+2]);
            av[r*4+3] = fmaf(xv, wv.w, av[r*4+3]);
        }
    }

    int n0 = nb + g * 4;

    // ---- scores: per-head partial sums, reduce across the 8 col-groups of each head ----
    float pq[4], pk[4];
#pragma unroll
    for (int r = 0; r < 4; r++) {
        float sQ = 0.f, sK = 0.f;
#pragma unroll
        for (int k = 0; k < 4; k++) {
            int c = c0 + k;
            sQ += tanh_fast(aq[r*4+k] + embS[c]) * aS[c & 31];
            sK += tanh_fast(ak[r*4+k] + embS[c]) * aS[32 + (c & 31)];
        }
        pq[r] = sQ; pk[r] = sK;
    }
#pragma unroll
    for (int m = 1; m < 8; m <<= 1) {
#pragma unroll
        for (int r = 0; r < 4; r++) {
            pq[r] += __shfl_xor_sync(0xffffffffu, pq[r], m);
            pk[r] += __shfl_xor_sync(0xffffffffu, pk[r], m);
        }
    }
    if ((cg & 7) == 0) {
        int h = cg >> 3;    // cg==0 -> head 0, cg==8 -> head 1
#pragma unroll
        for (int r = 0; r < 4; r++) {
            int n = n0 + r;
            if (n < NN) { sq[n * 2 + h] = pq[r]; sk[n * 2 + h] = pk[r]; }
        }
    }

    // ---- V: store permuted (v + rel): position s = (c%8)*8 + c/8 ----
#pragma unroll
    for (int r = 0; r < 4; r++) {
        int n = n0 + r;
        if (n < NN) {
#pragma unroll
            for (int k = 0; k < 4; k++) {
                int c = c0 + k;
                int s = (c & 7) * 8 + (c >> 3);
                vout[(size_t)n * 64 + s] = av[r*4+k] + relS[c];
            }
        }
    }
}

// ---------------- merged edge pass: 8 threads/edge, eb folded into agg ----------------
__global__ void __launch_bounds__(256) edge_kernel(
    const float* __restrict__ ea1, const int* __restrict__ row1, const int* __restrict__ col1,
    const float* __restrict__ ea2, const int* __restrict__ row2, const int* __restrict__ col2,
    const float* __restrict__ We, const float* __restrict__ a_attn)
{
    int bb = blockIdx.x;
    int relid = (bb >= EGB) ? 1 : 0;
    if (relid) bb -= EGB;

    const float* ea  = relid ? ea2  : ea1;
    const int*   row = relid ? row2 : row1;
    const int*   col = relid ? col2 : col1;
    const float* sq  = relid ? g_sq_a : g_sq_b;   // destination-node q scalar
    const float* sk  = relid ? g_sk_b : g_sk_a;   // source-node k scalar
    const float* vsrc = relid ? g_v2 : g_v1;
    float* agg = relid ? g_agg2 : g_agg1;
    float* den = relid ? g_den2 : g_den1;

    __shared__ float WeS[16][64];
    __shared__ float a4S[32];
    int tid = threadIdx.x;
    for (int i = tid; i < 1024; i += 256) WeS[i >> 6][i & 63] = We[i];
    if (tid < 32) a4S[tid] = a_attn[96 + tid];
    __syncthreads();

    int lane = tid & 7;
    int grp  = tid >> 3;

#pragma unroll 1
    for (int it = 0; it < 4; it++) {
        int e = (bb * 4 + it) * 32 + grp;
        int r = __ldg(row + e), c = __ldg(col + e);

        const float4* ea4p = (const float4*)ea + (size_t)e * 4;
        float4 A = __ldg(ea4p), B = __ldg(ea4p + 1), C = __ldg(ea4p + 2), D = __ldg(ea4p + 3);
        float ear[16] = {A.x, A.y, A.z, A.w, B.x, B.y, B.z, B.w,
                         C.x, C.y, C.z, C.w, D.x, D.y, D.z, D.w};

        // eb GEMV: this lane owns cols {lane + 8i}, i = 0..7 (conflict-free smem)
        float acc[8];
#pragma unroll
        for (int i = 0; i < 8; i++) acc[i] = 0.f;
#pragma unroll
        for (int j = 0; j < 16; j++) {
            float ev = ear[j];
#pragma unroll
            for (int i = 0; i < 8; i++)
                acc[i] = fmaf(ev, WeS[j][lane + 8 * i], acc[i]);
        }

        // score: col lane+8i -> head = (i>=4); a index = col % 32
        float se0 = 0.f, se1 = 0.f;
#pragma unroll
        for (int i = 0; i < 4; i++) se0 += tanh_fast(acc[i])     * a4S[lane + 8 * i];
#pragma unroll
        for (int i = 4; i < 8; i++) se1 += tanh_fast(acc[i])     * a4S[lane + 8 * (i - 4)];
#pragma unroll
        for (int m = 1; m < 8; m <<= 1) {
            se0 += __shfl_xor_sync(0xffffffffu, se0, m);
            se1 += __shfl_xor_sync(0xffffffffu, se1, m);
        }

        float2 sqv = __ldg((const float2*)sq + c);
        float2 skv = __ldg((const float2*)sk + r);
        float ex0 = __expf(sqv.x + skv.x + se0);
        float ex1 = __expf(sqv.y + skv.y + se1);

        if (lane == 0) red2(den + c * 2, ex0, ex1);

        // permuted v gather: contiguous 8 floats per lane = cols {lane+8i}
        const float4* vp = (const float4*)vsrc + (size_t)r * 16 + lane * 2;
        float4 v0 = __ldg(vp), v1 = __ldg(vp + 1);

        float* ap = agg + (size_t)c * 64 + lane * 8;
        red4(ap,     ex0 * (v0.x + acc[0]), ex0 * (v0.y + acc[1]),
                     ex0 * (v0.z + acc[2]), ex0 * (v0.w + acc[3]));
        red4(ap + 4, ex1 * (v1.x + acc[4]), ex1 * (v1.y + acc[5]),
                     ex1 * (v1.z + acc[6]), ex1 * (v1.w + acc[7]));
    }
}

// ---------------- final: out = (agg/den)@Wo + bo + x@Wr  (both types via grid.y) ----------------
__global__ void __launch_bounds__(256) final_kernel(
    const float* __restrict__ Wo_a, const float* __restrict__ bo_a,
    const float* __restrict__ x_a,  const float* __restrict__ Wr_a,
    const float* __restrict__ Wo_b, const float* __restrict__ bo_b,
    const float* __restrict__ x_b,  const float* __restrict__ Wr_b,
    float* __restrict__ out)
{
    int type = blockIdx.y;   // 0 = a, 1 = b
    const float* Wo = type ? Wo_b : Wo_a;
    const float* bo = type ? bo_b : bo_a;
    const float* x  = type ? x_b  : x_a;
    const float* Wr = type ? Wr_b : Wr_a;
    const float* agg = type ? g_agg1 : g_agg2;   // a's messages come from relation 2
    const float* den = type ? g_den1 : g_den2;
    float* outp = out + (size_t)type * NN * 32;

    __shared__ float afs[32][65];    // normalized, permuted-column order
    __shared__ float xs[32][65];
    __shared__ float WoP[64][32];    // rows permuted: WoP[s] = Wo[pi(s)]
    __shared__ float WrS[64][32];
    __shared__ float denS[32][2];
    __shared__ float boS[32];

    int tid = threadIdx.x;
    int nb  = blockIdx.x * 32;

    if (tid < 64) {
        int n2 = nb + (tid >> 1);
        denS[tid >> 1][tid & 1] = (n2 < NN) ? den[n2 * 2 + (tid & 1)] : 0.f;
    }
    if (tid < 32) boS[tid] = bo[tid];
    __syncthreads();

    for (int i = tid; i < 2048; i += 256) {
        int s = i >> 5, o = i & 31;
        WoP[s][o] = Wo[((s & 7) * 8 + (s >> 3)) * 32 + o];
        WrS[s][o] = Wr[s * 32 + o];
        int n2 = nb + (i >> 6), c2 = i & 63;
        float d = denS[i >> 6][((c2 & 7) >= 4) ? 1 : 0];
        float av = (n2 < NN) ? agg[(size_t)n2 * 64 + c2] : 0.f;
        afs[i >> 6][c2] = (d > 0.f) ? av / d : 0.f;
        xs[i >> 6][c2]  = (n2 < NN) ? x[(size_t)n2 * 64 + c2] : 0.f;
    }
    __syncthreads();

    int nl = tid >> 3, p = tid & 7;
    int n = nb + nl;

    float o[4];
#pragma unroll
    for (int i = 0; i < 4; i++) o[i] = boS[p * 4 + i];
#pragma unroll 8
    for (int k = 0; k < 64; k++) {
        float a  = afs[nl][k];   // column pi(k), matches WoP row k
        float xv = xs[nl][k];
#pragma unroll
        for (int i = 0; i < 4; i++) {
            o[i] = fmaf(a,  WoP[k][p * 4 + i], o[i]);
            o[i] = fmaf(xv, WrS[k][p * 4 + i], o[i]);
        }
    }
    if (n < NN) {
        float4* op = (float4*)(outp + (size_t)n * 32 + p * 4);
        op[0] = make_float4(o[0], o[1], o[2], o[3]);
    }
}

// ---------------- launch ----------------
extern "C" void kernel_launch(void* const* d_in, const int* in_sizes, int n_in,
                              void* d_out, int out_size)
{
    const float* x_a    = (const float*)d_in[0];
    const float* x_b    = (const float*)d_in[1];
    const float* ea1    = (const float*)d_in[2];
    const float* ea2    = (const float*)d_in[3];
    const float* Wq_a   = (const float*)d_in[4];
    const float* Wk_a   = (const float*)d_in[5];
    const float* Wv_a   = (const float*)d_in[6];
    const float* Wq_b   = (const float*)d_in[7];
    const float* Wk_b   = (const float*)d_in[8];
    const float* Wv_b   = (const float*)d_in[9];
    const float* emb_a  = (const float*)d_in[10];
    const float* emb_b  = (const float*)d_in[11];
    const float* rel1   = (const float*)d_in[12];
    const float* rel2   = (const float*)d_in[13];
    const float* We     = (const float*)d_in[14];
    const float* a_attn = (const float*)d_in[15];
    const float* Wo_a   = (const float*)d_in[16];
    const float* bo_a   = (const float*)d_in[17];
    const float* Wo_b   = (const float*)d_in[18];
    const float* bo_b   = (const float*)d_in[19];
    const float* Wr_a   = (const float*)d_in[20];
    const float* Wr_b   = (const float*)d_in[21];
    const int*   row1   = (const int*)d_in[22];
    const int*   col1   = (const int*)d_in[23];
    const int*   row2   = (const int*)d_in[24];
    const int*   col2   = (const int*)d_in[25];
    float* out = (float*)d_out;

    cudaFuncSetAttribute(prep_kernel, cudaFuncAttributeMaxDynamicSharedMemorySize, PREP_SMEM);

    prep_kernel<<<ZB + 2 * NB, 256, PREP_SMEM>>>(x_a, Wq_a, Wk_a, Wv_a,
                                                 x_b, Wq_b, Wk_b, Wv_b,
                                                 emb_a, emb_b, rel1, rel2, a_attn);

    edge_kernel<<<2 * EGB, 256>>>(ea1, row1, col1, ea2, row2, col2, We, a_attn);

    dim3 fg((NN + 31) / 32, 2);
    final_kernel<<<fg, 256>>>(Wo_a, bo_a, x_a, Wr_a,
                              Wo_b, bo_b, x_b, Wr_b, out);
}

// round 6
// speedup vs baseline: 1.9979x; 1.0388x over previous
#include <cuda_runtime.h>
#include <cstdint>

#define NN 50000
#define EE 800000
#define ZB 256          // zeroing blocks in prep kernel
#define NB 782          // node blocks per type: ceil(50000/64)
#define EGB 6250        // edge blocks per relation (128 edges/block)

// ---------------- scratch (device globals; no allocation allowed) ----------------
__device__ __align__(16) float g_sq_a[NN * 2];
__device__ __align__(16) float g_sk_a[NN * 2];
__device__ __align__(16) float g_sq_b[NN * 2];
__device__ __align__(16) float g_sk_b[NN * 2];
__device__ __align__(16) float g_v1[NN * 64];     // v_a + rel1 (natural col order)
__device__ __align__(16) float g_v2[NN * 64];     // v_b + rel2
__device__ __align__(16) float g_agg1[NN * 64];   // Σ ex*(v+rel+eb), dst = b
__device__ __align__(16) float g_agg2[NN * 64];   // dst = a
__device__ __align__(16) float g_den1[NN * 2];    // Σ ex
__device__ __align__(16) float g_den2[NN * 2];

// ---------------- helpers ----------------
__device__ __forceinline__ float tanh_fast(float x) {
    float y;
    asm("tanh.approx.f32 %0, %1;" : "=f"(y) : "f"(x));
    return y;
}
__device__ __forceinline__ void red4(float* p, float a, float b, float c, float d) {
    asm volatile("red.global.add.v4.f32 [%0], {%1,%2,%3,%4};"
                 :: "l"(p), "f"(a), "f"(b), "f"(c), "f"(d) : "memory");
}
__device__ __forceinline__ void red2(float* p, float a, float b) {
    asm volatile("red.global.add.v2.f32 [%0], {%1,%2};"
                 :: "l"(p), "f"(a), "f"(b) : "memory");
}

// ---------------- prep: zero scratch + fused-QKV node precompute ----------------
// 512 threads/block, 64 nodes/block; thread tile = 2 nodes x 4 cols x 3 matrices
// dynamic smem: xs[64*65] | Wq[4096] | Wk[4096] | Wv[4096] | emb[64] | rel[64] | a[64]
#define PREP_SMEM ((4160 + 3 * 4096 + 192) * 4)

__global__ void __launch_bounds__(512) prep_kernel(
    const float* __restrict__ x_a, const float* __restrict__ Wq_a,
    const float* __restrict__ Wk_a, const float* __restrict__ Wv_a,
    const float* __restrict__ x_b, const float* __restrict__ Wq_b,
    const float* __restrict__ Wk_b, const float* __restrict__ Wv_b,
    const float* __restrict__ emb_a, const float* __restrict__ emb_b,
    const float* __restrict__ rel1, const float* __restrict__ rel2,
    const float* __restrict__ a_attn)
{
    int b = blockIdx.x;
    int tid = threadIdx.x;

    if (b < ZB) {
        const float4 z = make_float4(0.f, 0.f, 0.f, 0.f);
        int i = b * 512 + tid;
        const int S = ZB * 512;
        for (int k = i; k < NN * 16; k += S) { ((float4*)g_agg1)[k] = z; ((float4*)g_agg2)[k] = z; }
        for (int k = i; k < NN / 2;  k += S) { ((float4*)g_den1)[k] = z; ((float4*)g_den2)[k] = z; }
        return;
    }
    b -= ZB;
    int type = (b >= NB) ? 1 : 0;
    if (type) b -= NB;

    const float* x   = type ? x_b  : x_a;
    const float* Wqg = type ? Wq_b : Wq_a;
    const float* Wkg = type ? Wk_b : Wk_a;
    const float* Wvg = type ? Wv_b : Wv_a;
    const float* emb = type ? emb_b : emb_a;
    const float* rel = type ? rel2 : rel1;
    float* sq   = type ? g_sq_b : g_sq_a;
    float* sk   = type ? g_sk_b : g_sk_a;
    float* vout = type ? g_v2   : g_v1;

    extern __shared__ float sm[];
    float* xs   = sm;              // 64 x 65
    float* Wq   = sm + 4160;
    float* Wk   = Wq + 4096;
    float* Wv   = Wk + 4096;
    float* embS = Wv + 4096;
    float* relS = embS + 64;
    float* aS   = relS + 64;

    int nb = b * 64;

    for (int i = tid; i < 4096; i += 512) {
        int rr = i >> 6, cc = i & 63;
        int n2 = nb + rr;
        xs[rr * 65 + cc] = (n2 < NN) ? __ldg(x + n2 * 64 + cc) : 0.f;
        Wq[i] = __ldg(Wqg + i);
        Wk[i] = __ldg(Wkg + i);
        Wv[i] = __ldg(Wvg + i);
    }
    if (tid < 64) { embS[tid] = emb[tid]; relS[tid] = rel[tid]; aS[tid] = a_attn[tid]; }
    __syncthreads();

    int g = tid >> 4, cg = tid & 15, c0 = cg * 4;   // g: node pair 0..31

    float aq[8], ak[8], av[8];
#pragma unroll
    for (int i = 0; i < 8; i++) { aq[i] = 0.f; ak[i] = 0.f; av[i] = 0.f; }

#pragma unroll 8
    for (int j = 0; j < 64; j++) {
        float4 wq = *(const float4*)&Wq[j * 64 + c0];
        float4 wk = *(const float4*)&Wk[j * 64 + c0];
        float4 wv = *(const float4*)&Wv[j * 64 + c0];
        float x0 = xs[(g * 2 + 0) * 65 + j];
        float x1 = xs[(g * 2 + 1) * 65 + j];
        aq[0] = fmaf(x0, wq.x, aq[0]); aq[1] = fmaf(x0, wq.y, aq[1]);
        aq[2] = fmaf(x0, wq.z, aq[2]); aq[3] = fmaf(x0, wq.w, aq[3]);
        aq[4] = fmaf(x1, wq.x, aq[4]); aq[5] = fmaf(x1, wq.y, aq[5]);
        aq[6] = fmaf(x1, wq.z, aq[6]); aq[7] = fmaf(x1, wq.w, aq[7]);
        ak[0] = fmaf(x0, wk.x, ak[0]); ak[1] = fmaf(x0, wk.y, ak[1]);
        ak[2] = fmaf(x0, wk.z, ak[2]); ak[3] = fmaf(x0, wk.w, ak[3]);
        ak[4] = fmaf(x1, wk.x, ak[4]); ak[5] = fmaf(x1, wk.y, ak[5]);
        ak[6] = fmaf(x1, wk.z, ak[6]); ak[7] = fmaf(x1, wk.w, ak[7]);
        av[0] = fmaf(x0, wv.x, av[0]); av[1] = fmaf(x0, wv.y, av[1]);
        av[2] = fmaf(x0, wv.z, av[2]); av[3] = fmaf(x0, wv.w, av[3]);
        av[4] = fmaf(x1, wv.x, av[4]); av[5] = fmaf(x1, wv.y, av[5]);
        av[6] = fmaf(x1, wv.z, av[6]); av[7] = fmaf(x1, wv.w, av[7]);
    }

    int n0 = nb + g * 2;

    // ---- scores: reduce across the 8 col-groups of each head (16-lane halves) ----
    float pq[2], pk[2];
#pragma unroll
    for (int r = 0; r < 2; r++) {
        float sQ = 0.f, sK = 0.f;
#pragma unroll
        for (int k = 0; k < 4; k++) {
            int c = c0 + k;
            sQ += tanh_fast(aq[r * 4 + k] + embS[c]) * aS[c & 31];
            sK += tanh_fast(ak[r * 4 + k] + embS[c]) * aS[32 + (c & 31)];
        }
        pq[r] = sQ; pk[r] = sK;
    }
#pragma unroll
    for (int m = 1; m < 8; m <<= 1) {
#pragma unroll
        for (int r = 0; r < 2; r++) {
            pq[r] += __shfl_xor_sync(0xffffffffu, pq[r], m);
            pk[r] += __shfl_xor_sync(0xffffffffu, pk[r], m);
        }
    }
    if ((cg & 7) == 0) {
        int h = cg >> 3;
#pragma unroll
        for (int r = 0; r < 2; r++) {
            int n = n0 + r;
            if (n < NN) { sq[n * 2 + h] = pq[r]; sk[n * 2 + h] = pk[r]; }
        }
    }

    // ---- V: store (v + rel) in natural column order ----
#pragma unroll
    for (int r = 0; r < 2; r++) {
        int n = n0 + r;
        if (n < NN) {
            *(float4*)(vout + (size_t)n * 64 + c0) =
                make_float4(av[r*4+0] + relS[c0+0], av[r*4+1] + relS[c0+1],
                            av[r*4+2] + relS[c0+2], av[r*4+3] + relS[c0+3]);
        }
    }
}

// ---------------- merged edge pass: 8 threads/edge ----------------
// lane l owns cols {4l..4l+3} (head 0) and {32+4l..32+4l+3} (head 1):
// We reads become two conflict-free LDS.128 per j; v/agg stay natural + contiguous.
__global__ void __launch_bounds__(256) edge_kernel(
    const float* __restrict__ ea1, const int* __restrict__ row1, const int* __restrict__ col1,
    const float* __restrict__ ea2, const int* __restrict__ row2, const int* __restrict__ col2,
    const float* __restrict__ We, const float* __restrict__ a_attn)
{
    int bb = blockIdx.x;
    int relid = (bb >= EGB) ? 1 : 0;
    if (relid) bb -= EGB;

    const float* ea  = relid ? ea2  : ea1;
    const int*   row = relid ? row2 : row1;
    const int*   col = relid ? col2 : col1;
    const float* sq  = relid ? g_sq_a : g_sq_b;   // destination-node q scalar
    const float* sk  = relid ? g_sk_b : g_sk_a;   // source-node k scalar
    const float* vsrc = relid ? g_v2 : g_v1;
    float* agg = relid ? g_agg2 : g_agg1;
    float* den = relid ? g_den2 : g_den1;

    __shared__ __align__(16) float WeS[1024];     // [16][64] natural
    __shared__ float a4S[32];
    int tid = threadIdx.x;
    for (int i = tid; i < 1024; i += 256) WeS[i] = We[i];
    if (tid < 32) a4S[tid] = a_attn[96 + tid];
    __syncthreads();

    int lane = tid & 7;
    int grp  = tid >> 3;
    const float4* WeV = (const float4*)WeS;       // row j = 16 float4s

#pragma unroll 1
    for (int it = 0; it < 4; it++) {
        int e = (bb * 4 + it) * 32 + grp;
        int r = __ldg(row + e), c = __ldg(col + e);

        const float4* ea4p = (const float4*)ea + (size_t)e * 4;
        float4 A = __ldg(ea4p), B = __ldg(ea4p + 1), C = __ldg(ea4p + 2), D = __ldg(ea4p + 3);
        float ear[16] = {A.x, A.y, A.z, A.w, B.x, B.y, B.z, B.w,
                         C.x, C.y, C.z, C.w, D.x, D.y, D.z, D.w};

        float acc[8];
#pragma unroll
        for (int i = 0; i < 8; i++) acc[i] = 0.f;
#pragma unroll
        for (int j = 0; j < 16; j++) {
            float ev = ear[j];
            float4 w0 = WeV[j * 16 + lane];        // cols 4l..4l+3
            float4 w1 = WeV[j * 16 + 8 + lane];    // cols 32+4l..32+4l+3
            acc[0] = fmaf(ev, w0.x, acc[0]); acc[1] = fmaf(ev, w0.y, acc[1]);
            acc[2] = fmaf(ev, w0.z, acc[2]); acc[3] = fmaf(ev, w0.w, acc[3]);
            acc[4] = fmaf(ev, w1.x, acc[4]); acc[5] = fmaf(ev, w1.y, acc[5]);
            acc[6] = fmaf(ev, w1.z, acc[6]); acc[7] = fmaf(ev, w1.w, acc[7]);
        }

        // score: head0 cols 4l+t (a idx 4l+t), head1 cols 32+4l+t (a idx 4l+t)
        float se0 = 0.f, se1 = 0.f;
#pragma unroll
        for (int t = 0; t < 4; t++) {
            float av = a4S[4 * lane + t];
            se0 += tanh_fast(acc[t])     * av;
            se1 += tanh_fast(acc[4 + t]) * av;
        }
#pragma unroll
        for (int m = 1; m < 8; m <<= 1) {
            se0 += __shfl_xor_sync(0xffffffffu, se0, m);
            se1 += __shfl_xor_sync(0xffffffffu, se1, m);
        }

        float2 sqv = __ldg((const float2*)sq + c);
        float2 skv = __ldg((const float2*)sk + r);
        float ex0 = __expf(sqv.x + skv.x + se0);
        float ex1 = __expf(sqv.y + skv.y + se1);

        if (lane == 0) red2(den + c * 2, ex0, ex1);

        // v gather: natural layout, contiguous per 8-lane group
        const float4* vp = (const float4*)vsrc + (size_t)r * 16;
        float4 v0 = __ldg(vp + lane);              // cols 4l..4l+3
        float4 v1 = __ldg(vp + 8 + lane);          // cols 32+4l..

        float* ap = agg + (size_t)c * 64;
        red4(ap + 4 * lane,
             ex0 * (v0.x + acc[0]), ex0 * (v0.y + acc[1]),
             ex0 * (v0.z + acc[2]), ex0 * (v0.w + acc[3]));
        red4(ap + 32 + 4 * lane,
             ex1 * (v1.x + acc[4]), ex1 * (v1.y + acc[5]),
             ex1 * (v1.z + acc[6]), ex1 * (v1.w + acc[7]));
    }
}

// ---------------- final: out = (agg/den)@Wo + bo + x@Wr  (both types via grid.y) ----------------
__global__ void __launch_bounds__(256) final_kernel(
    const float* __restrict__ Wo_a, const float* __restrict__ bo_a,
    const float* __restrict__ x_a,  const float* __restrict__ Wr_a,
    const float* __restrict__ Wo_b, const float* __restrict__ bo_b,
    const float* __restrict__ x_b,  const float* __restrict__ Wr_b,
    float* __restrict__ out)
{
    int type = blockIdx.y;   // 0 = a, 1 = b
    const float* Wo = type ? Wo_b : Wo_a;
    const float* bo = type ? bo_b : bo_a;
    const float* x  = type ? x_b  : x_a;
    const float* Wr = type ? Wr_b : Wr_a;
    const float* agg = type ? g_agg1 : g_agg2;   // a's messages come from relation 2
    const float* den = type ? g_den1 : g_den2;
    float* outp = out + (size_t)type * NN * 32;

    __shared__ float afs[32][65];
    __shared__ float xs[32][65];
    __shared__ float WoS[64][32];
    __shared__ float WrS[64][32];
    __shared__ float denS[32][2];
    __shared__ float boS[32];

    int tid = threadIdx.x;
    int nb  = blockIdx.x * 32;

    if (tid < 64) {
        int n2 = nb + (tid >> 1);
        denS[tid >> 1][tid & 1] = (n2 < NN) ? den[n2 * 2 + (tid & 1)] : 0.f;
    }
    if (tid < 32) boS[tid] = bo[tid];
    __syncthreads();

    for (int i = tid; i < 2048; i += 256) {
        int s = i >> 5, o = i & 31;
        WoS[s][o] = Wo[s * 32 + o];
        WrS[s][o] = Wr[s * 32 + o];
        int n2 = nb + (i >> 6), c2 = i & 63;
        float d = denS[i >> 6][c2 >> 5];
        float av = (n2 < NN) ? agg[(size_t)n2 * 64 + c2] : 0.f;
        afs[i >> 6][c2] = (d > 0.f) ? av / d : 0.f;
        xs[i >> 6][c2]  = (n2 < NN) ? x[(size_t)n2 * 64 + c2] : 0.f;
    }
    __syncthreads();

    int nl = tid >> 3, p = tid & 7;
    int n = nb + nl;

    float o[4];
#pragma unroll
    for (int i = 0; i < 4; i++) o[i] = boS[p * 4 + i];
#pragma unroll 8
    for (int k = 0; k < 64; k++) {
        float a  = afs[nl][k];
        float xv = xs[nl][k];
#pragma unroll
        for (int i = 0; i < 4; i++) {
            o[i] = fmaf(a,  WoS[k][p * 4 + i], o[i]);
            o[i] = fmaf(xv, WrS[k][p * 4 + i], o[i]);
        }
    }
    if (n < NN) {
        float4* op = (float4*)(outp + (size_t)n * 32 + p * 4);
        op[0] = make_float4(o[0], o[1], o[2], o[3]);
    }
}

// ---------------- launch ----------------
extern "C" void kernel_launch(void* const* d_in, const int* in_sizes, int n_in,
                              void* d_out, int out_size)
{
    const float* x_a    = (const float*)d_in[0];
    const float* x_b    = (const float*)d_in[1];
    const float* ea1    = (const float*)d_in[2];
    const float* ea2    = (const float*)d_in[3];
    const float* Wq_a   = (const float*)d_in[4];
    const float* Wk_a   = (const float*)d_in[5];
    const float* Wv_a   = (const float*)d_in[6];
    const float* Wq_b   = (const float*)d_in[7];
    const float* Wk_b   = (const float*)d_in[8];
    const float* Wv_b   = (const float*)d_in[9];
    const float* emb_a  = (const float*)d_in[10];
    const float* emb_b  = (const float*)d_in[11];
    const float* rel1   = (const float*)d_in[12];
    const float* rel2   = (const float*)d_in[13];
    const float* We     = (const float*)d_in[14];
    const float* a_attn = (const float*)d_in[15];
    const float* Wo_a   = (const float*)d_in[16];
    const float* bo_a   = (const float*)d_in[17];
    const float* Wo_b   = (const float*)d_in[18];
    const float* bo_b   = (const float*)d_in[19];
    const float* Wr_a   = (const float*)d_in[20];
    const float* Wr_b   = (const float*)d_in[21];
    const int*   row1   = (const int*)d_in[22];
    const int*   col1   = (const int*)d_in[23];
    const int*   row2   = (const int*)d_in[24];
    const int*   col2   = (const int*)d_in[25];
    float* out = (float*)d_out;

    cudaFuncSetAttribute(prep_kernel, cudaFuncAttributeMaxDynamicSharedMemorySize, PREP_SMEM);

    prep_kernel<<<ZB + 2 * NB, 512, PREP_SMEM>>>(x_a, Wq_a, Wk_a, Wv_a,
                                                 x_b, Wq_b, Wk_b, Wv_b,
                                                 emb_a, emb_b, rel1, rel2, a_attn);

    edge_kernel<<<2 * EGB, 256>>>(ea1, row1, col1, ea2, row2, col2, We, a_attn);

    dim3 fg((NN + 31) / 32, 2);
    final_kernel<<<fg, 256>>>(Wo_a, bo_a, x_a, Wr_a,
                              Wo_b, bo_b, x_b, Wr_b, out);
}